// round 7
// baseline (speedup 1.0000x reference)
#include <cuda_runtime.h>

// ---------------------------------------------------------------------------
// SNN: 20 steps, batch 8192, 676 -> 256 (LIF) -> 10 (LIF)
// Outputs concatenated in tuple order: spk2, spk1, mem2, mem1 (fp32)
//
// NUMERICS FROZEN (passed round 6, rel_err 6.0e-4):
//   * layer-1: per-16k-tile fma2 chains + Kahan-compensated cross-tile fold
//   * layer-2: serial ascending-k fp32 fmaf chain, single accumulator
//   * bias after GEMM; LIF beta*m+h as separate mul/add; sub-reset
// This round changes ONLY scheduling/memory placement:
//   * l1: Kahan nc[] moved from registers to SMEM (kills reg spills)
//   * l2: thread per (row,output) = 81920 threads, coalesced SMEM staging
// ---------------------------------------------------------------------------

#define NS    20
#define BATCH 8192
#define NIN   676
#define NHID  256
#define NOUTN 10

#define KT  16
#define NKT 43          // ceil(676/16)
#define BM  128
#define BN  128

#define SPK2_OFF 0ull
#define SPK1_OFF (20ull*8192*10)
#define MEM2_OFF (SPK1_OFF + 20ull*8192*256)
#define MEM1_OFF (MEM2_OFF + 20ull*8192*10)

typedef unsigned long long u64;

__device__ __forceinline__ u64 bcast2(float x) {
    u64 r; asm("mov.b64 %0, {%1, %1};" : "=l"(r) : "f"(x)); return r;
}
__device__ __forceinline__ void upk2(u64 v, float& a, float& b) {
    asm("mov.b64 {%0, %1}, %2;" : "=f"(a), "=f"(b) : "l"(v));
}
__device__ __forceinline__ void fma2(u64& d, u64 a, u64 b) {
    asm("fma.rn.f32x2 %0, %1, %2, %0;" : "+l"(d) : "l"(a), "l"(b));
}
__device__ __forceinline__ u64 add2(u64 a, u64 b) {
    u64 r; asm("add.rn.f32x2 %0, %1, %2;" : "=l"(r) : "l"(a), "l"(b));
    return r;
}
// negate both packed floats (sign-bit xor); x + (-y) == x - y exactly (rn)
__device__ __forceinline__ u64 neg2(u64 a) {
    return a ^ 0x8000000080000000ull;
}

// ---------------------------------------------------------------------------
// Kernel 1: fused  h1 = x_t @ W1^T + b1 ; LIF over t  -> spk1, mem1
// Grid: (BATCH/BM, NHID/BN), 256 threads, 8x8 per-thread tile.
// Dynamic SMEM (160 KB):
//   [buf0: xs 2048 | ws 2048][buf1: xs 2048 | ws 2048]  32 KB
//   [membrane 128x128]                                  64 KB
//   [Kahan nc, 32 u64 per thread]                       64 KB
// Arithmetic identical to round 6 (Kahan fold; nc now lives in SMEM).
// ---------------------------------------------------------------------------
__global__ void __launch_bounds__(256, 1) snn_l1(
    const float* __restrict__ x, const float* __restrict__ W1,
    const float* __restrict__ b1, float* __restrict__ out)
{
    extern __shared__ float sm[];
    float* msm = sm + 8192;                       // 16384 floats
    u64*   ncp = (u64*)(sm + 8192 + 16384);       // 32 u64 per thread

    const int tid  = threadIdx.x;
    const int b0   = blockIdx.x * BM;
    const int n0   = blockIdx.y * BN;
    const int row0 = (tid >> 4) * 8;
    const int col0 = (tid & 15) * 8;

    const int li0 = tid >> 2;          // rows 0..63 ; second row = li0+64
    const int lk0 = (tid & 3) * 4;     // k offset within tile (0,4,8,12)

    // bias (added AFTER the K accumulation)
    float bcol[8];
#pragma unroll
    for (int j = 0; j < 8; j++) bcol[j] = b1[n0 + col0 + j];

    // init membrane
#pragma unroll
    for (int e = 0; e < 64; e++) msm[e*256 + tid] = 0.0f;

    const float4 z4 = make_float4(0.f, 0.f, 0.f, 0.f);
    float4 xr0, xr1, wr0, wr1;

    // prefetch tile (t=0, kt=0)
    {
        const int k = lk0;
        xr0 = *(const float4*)&x[(size_t)(b0 + li0)      * NIN + k];
        xr1 = *(const float4*)&x[(size_t)(b0 + li0 + 64) * NIN + k];
        wr0 = *(const float4*)&W1[(size_t)(n0 + li0)      * NIN + k];
        wr1 = *(const float4*)&W1[(size_t)(n0 + li0 + 64) * NIN + k];
    }
    {
        float* xs = sm;        float* ws = sm + 2048;
        xs[(lk0+0)*128 + li0] = xr0.x; xs[(lk0+1)*128 + li0] = xr0.y;
        xs[(lk0+2)*128 + li0] = xr0.z; xs[(lk0+3)*128 + li0] = xr0.w;
        xs[(lk0+0)*128 + li0+64] = xr1.x; xs[(lk0+1)*128 + li0+64] = xr1.y;
        xs[(lk0+2)*128 + li0+64] = xr1.z; xs[(lk0+3)*128 + li0+64] = xr1.w;
        ws[(lk0+0)*128 + li0] = wr0.x; ws[(lk0+1)*128 + li0] = wr0.y;
        ws[(lk0+2)*128 + li0] = wr0.z; ws[(lk0+3)*128 + li0] = wr0.w;
        ws[(lk0+0)*128 + li0+64] = wr1.x; ws[(lk0+1)*128 + li0+64] = wr1.y;
        ws[(lk0+2)*128 + li0+64] = wr1.z; ws[(lk0+3)*128 + li0+64] = wr1.w;
    }
    __syncthreads();

    u64 s[8][4];    // running sum (registers)
    int cur = 0, t = 0, kt = 0;

    for (int idx = 0; idx < NS * NKT; ++idx) {
        int nt = t, nkt = kt + 1;
        if (nkt == NKT) { nkt = 0; nt++; }
        const bool more = (idx + 1 < NS * NKT);

        // prefetch next tile into registers (latency hidden by compute)
        if (more) {
            const int k = nkt * KT + lk0;
            const float* xt = x + (size_t)nt * BATCH * NIN;
            if (k < NIN) {
                xr0 = *(const float4*)&xt[(size_t)(b0 + li0)      * NIN + k];
                xr1 = *(const float4*)&xt[(size_t)(b0 + li0 + 64) * NIN + k];
                wr0 = *(const float4*)&W1[(size_t)(n0 + li0)      * NIN + k];
                wr1 = *(const float4*)&W1[(size_t)(n0 + li0 + 64) * NIN + k];
            } else {
                xr0 = z4; xr1 = z4; wr0 = z4; wr1 = z4;
            }
        }

        if (kt == 0) {
#pragma unroll
            for (int i = 0; i < 8; i++)
#pragma unroll
                for (int jp = 0; jp < 4; jp++) {
                    s[i][jp] = 0ull;
                    ncp[(i*4 + jp)*256 + tid] = 0ull;
                }
        }

        // compute on current buffer: fresh per-tile accumulator q
        u64 q[8][4];
#pragma unroll
        for (int i = 0; i < 8; i++)
#pragma unroll
            for (int jp = 0; jp < 4; jp++) q[i][jp] = 0ull;
        {
            const float* xs = sm + cur * 4096;
            const float* ws = xs + 2048;
#pragma unroll
            for (int k = 0; k < KT; k++) {
                const float* xk = &xs[k*128 + row0];
                u64 xb[8];
                float2 p;
                p = *(const float2*)&xk[0]; xb[0] = bcast2(p.x); xb[1] = bcast2(p.y);
                p = *(const float2*)&xk[2]; xb[2] = bcast2(p.x); xb[3] = bcast2(p.y);
                p = *(const float2*)&xk[4]; xb[4] = bcast2(p.x); xb[5] = bcast2(p.y);
                p = *(const float2*)&xk[6]; xb[6] = bcast2(p.x); xb[7] = bcast2(p.y);
                const float* wk = &ws[k*128 + col0];
                u64 wp[4];
                wp[0] = *(const u64*)&wk[0];
                wp[1] = *(const u64*)&wk[2];
                wp[2] = *(const u64*)&wk[4];
                wp[3] = *(const u64*)&wk[6];
#pragma unroll
                for (int i = 0; i < 8; i++)
#pragma unroll
                    for (int jp = 0; jp < 4; jp++)
                        fma2(q[i][jp], xb[i], wp[jp]);
            }
        }
        // Kahan/Neumaier fold of tile sum q into (s, nc):  (nc in SMEM)
        //   y = q + nc; t = s + y; d = t - s; nc = y - d; s = t
#pragma unroll
        for (int i = 0; i < 8; i++)
#pragma unroll
            for (int jp = 0; jp < 4; jp++) {
                const int nidx = (i*4 + jp)*256 + tid;
                u64 ncv = ncp[nidx];
                u64 y  = add2(q[i][jp], ncv);
                u64 tt = add2(s[i][jp], y);
                u64 d  = add2(tt, neg2(s[i][jp]));
                ncp[nidx] = add2(y, neg2(d));
                s[i][jp] = tt;
            }

        // end of K: LIF update for timestep t, write spk1 / mem1
        if (kt == NKT - 1) {
            const size_t ob = ((size_t)t * BATCH + (b0 + row0)) * NHID + n0 + col0;
#pragma unroll
            for (int i = 0; i < 8; i++) {
                float h[8];
#pragma unroll
                for (int jp = 0; jp < 4; jp++) {
                    u64 ncv = ncp[(i*4 + jp)*256 + tid];
                    u64 hs = add2(s[i][jp], neg2(ncv));   // s + c
                    upk2(hs, h[2*jp], h[2*jp+1]);
                }
                float sv[8], mv[8];
#pragma unroll
                for (int j = 0; j < 8; j++) {
                    float hb = __fadd_rn(h[j], bcol[j]);        // gemm + bias
                    float mm = msm[(i*8 + j)*256 + tid];
                    mm = __fadd_rn(__fmul_rn(0.9f, mm), hb);    // beta*m + h
                    float spk = (mm - 1.0f > 0.0f) ? 1.0f : 0.0f;
                    mm = __fadd_rn(mm, -spk);                    // soft reset
                    msm[(i*8 + j)*256 + tid] = mm;
                    sv[j] = spk; mv[j] = mm;
                }
                float* o1 = out + SPK1_OFF + ob + (size_t)i * NHID;
                *(float4*)&o1[0] = make_float4(sv[0], sv[1], sv[2], sv[3]);
                *(float4*)&o1[4] = make_float4(sv[4], sv[5], sv[6], sv[7]);
                float* o2 = out + MEM1_OFF + ob + (size_t)i * NHID;
                *(float4*)&o2[0] = make_float4(mv[0], mv[1], mv[2], mv[3]);
                *(float4*)&o2[4] = make_float4(mv[4], mv[5], mv[6], mv[7]);
            }
        }

        // stage next tile into the other buffer
        if (more) {
            float* xs = sm + (cur ^ 1) * 4096;
            float* ws = xs + 2048;
            xs[(lk0+0)*128 + li0] = xr0.x; xs[(lk0+1)*128 + li0] = xr0.y;
            xs[(lk0+2)*128 + li0] = xr0.z; xs[(lk0+3)*128 + li0] = xr0.w;
            xs[(lk0+0)*128 + li0+64] = xr1.x; xs[(lk0+1)*128 + li0+64] = xr1.y;
            xs[(lk0+2)*128 + li0+64] = xr1.z; xs[(lk0+3)*128 + li0+64] = xr1.w;
            ws[(lk0+0)*128 + li0] = wr0.x; ws[(lk0+1)*128 + li0] = wr0.y;
            ws[(lk0+2)*128 + li0] = wr0.z; ws[(lk0+3)*128 + li0] = wr0.w;
            ws[(lk0+0)*128 + li0+64] = wr1.x; ws[(lk0+1)*128 + li0+64] = wr1.y;
            ws[(lk0+2)*128 + li0+64] = wr1.z; ws[(lk0+3)*128 + li0+64] = wr1.w;
        }
        __syncthreads();
        cur ^= 1; t = nt; kt = nkt;
    }
}

// ---------------------------------------------------------------------------
// Kernel 2: fused  h2 = spk1_t @ W2^T + b2 ; LIF over t  -> spk2, mem2
// Thread per (row, output): 256 CTAs x 320 threads (32 rows x 10 outputs).
// Spikes staged coalesced into SMEM (row stride 264 floats, conflict-free);
// W2 in SMEM (row stride 260). Each thread runs the IDENTICAL serial
// ascending-k fmaf chain (single fp32 accumulator) as the round-6 kernel,
// so spk2/mem2 remain bit-exact.
// ---------------------------------------------------------------------------
#define L2_ROWS 32
#define L2_TPB  (L2_ROWS * NOUTN)   // 320
#define SP_STRIDE 264               // 256 + 8 pad (float4-aligned, bank-safe)
#define W2_STRIDE 260               // 256 + 4 pad (float4-aligned)

__global__ void __launch_bounds__(L2_TPB) snn_l2(
    float* __restrict__ out, const float* __restrict__ W2,
    const float* __restrict__ b2)
{
    __shared__ float w2s[NOUTN * W2_STRIDE];
    __shared__ float sps[L2_ROWS * SP_STRIDE];

    const int tid = threadIdx.x;
    const int r   = tid / NOUTN;          // local row 0..31
    const int o   = tid % NOUTN;          // output 0..9
    const int row = blockIdx.x * L2_ROWS + r;

    // load W2 into padded SMEM
    for (int i = tid; i < NOUTN * NHID; i += L2_TPB) {
        int oo = i / NHID, kk = i % NHID;
        w2s[oo * W2_STRIDE + kk] = W2[i];
    }
    const float bo = b2[o];

    float m2 = 0.0f;

    for (int t = 0; t < NS; t++) {
        __syncthreads();   // previous iteration's reads done before overwrite
        // stage 32 rows x 256 spikes, coalesced float4
        {
            const float4* src = (const float4*)(out + SPK1_OFF +
                ((size_t)t * BATCH + (size_t)blockIdx.x * L2_ROWS) * NHID);
            for (int i = tid; i < L2_ROWS * (NHID/4); i += L2_TPB) {
                int rr = i >> 6;            // /64
                int kk = i & 63;
                float4 v = src[i];
                *(float4*)&sps[rr * SP_STRIDE + kk * 4] = v;
            }
        }
        __syncthreads();

        // serial ascending-k chain: acc = fma(s_k, w_k, acc), k = 0..255
        float acc = 0.0f;
        const float* sp = &sps[r * SP_STRIDE];
        const float* wo = &w2s[o * W2_STRIDE];
#pragma unroll
        for (int kc = 0; kc < NHID / 4; kc++) {
            float4 v = *(const float4*)&sp[kc * 4];
            float4 w = *(const float4*)&wo[kc * 4];
            acc = fmaf(v.x, w.x, acc);
            acc = fmaf(v.y, w.y, acc);
            acc = fmaf(v.z, w.z, acc);
            acc = fmaf(v.w, w.w, acc);
        }

        float h = __fadd_rn(acc, bo);                 // gemm + bias
        m2 = __fadd_rn(__fmul_rn(0.9f, m2), h);       // beta*m + h
        float spk = (m2 - 1.0f > 0.0f) ? 1.0f : 0.0f;
        m2 = __fadd_rn(m2, -spk);                     // soft reset

        const size_t ob = ((size_t)t * BATCH + row) * NOUTN + o;
        out[SPK2_OFF + ob] = spk;
        out[MEM2_OFF + ob] = m2;
    }
}

// ---------------------------------------------------------------------------
extern "C" void kernel_launch(void* const* d_in, const int* in_sizes, int n_in,
                              void* d_out, int out_size)
{
    const float* x  = (const float*)d_in[0];
    const float* W1 = (const float*)d_in[1];
    const float* b1 = (const float*)d_in[2];
    const float* W2 = (const float*)d_in[3];
    const float* b2 = (const float*)d_in[4];
    float* out = (float*)d_out;

    cudaFuncSetAttribute(snn_l1, cudaFuncAttributeMaxDynamicSharedMemorySize,
                         160 * 1024);

    dim3 g1(BATCH / BM, NHID / BN);
    snn_l1<<<g1, 256, 160 * 1024>>>(x, W1, b1, out);
    snn_l2<<<BATCH / L2_ROWS, L2_TPB>>>(out, W2, b2);
}

// round 9
// speedup vs baseline: 1.1440x; 1.1440x over previous
#include <cuda_runtime.h>
#include <cstdint>

// ---------------------------------------------------------------------------
// SNN: 20 steps, batch 8192, 676 -> 256 (LIF) -> 10 (LIF)
// Outputs concatenated in tuple order: spk2, spk1, mem2, mem1 (fp32)
//
// NUMERICS FROZEN (passed rounds 6/7, rel_err 6.03e-4):
//   * layer-1: per-16k-tile fma2 chains + Kahan-compensated cross-tile fold
//   * layer-2: serial ascending-k fp32 fmaf chain, single accumulator
//   * bias after GEMM; LIF beta*m+h as separate mul/add; sub-reset
// Round 9 = round 8 + missing <cstdint> (scheduling only, bit-identical):
//   * l1: Kahan nc in REGISTERS (round-7 SMEM version cost +250us)
//   * l1: first k of each tile uses mul.rn.f32x2 (== fma(a,b,0), exact)
//   * l2: cp.async double-buffered staging, 512 CTAs
// ---------------------------------------------------------------------------

#define NS    20
#define BATCH 8192
#define NIN   676
#define NHID  256
#define NOUTN 10

#define KT  16
#define NKT 43          // ceil(676/16)
#define BM  128
#define BN  128

#define SPK2_OFF 0ull
#define SPK1_OFF (20ull*8192*10)
#define MEM2_OFF (SPK1_OFF + 20ull*8192*256)
#define MEM1_OFF (MEM2_OFF + 20ull*8192*10)

typedef unsigned long long u64;

__device__ __forceinline__ u64 bcast2(float x) {
    u64 r; asm("mov.b64 %0, {%1, %1};" : "=l"(r) : "f"(x)); return r;
}
__device__ __forceinline__ void upk2(u64 v, float& a, float& b) {
    asm("mov.b64 {%0, %1}, %2;" : "=f"(a), "=f"(b) : "l"(v));
}
__device__ __forceinline__ void fma2(u64& d, u64 a, u64 b) {
    asm("fma.rn.f32x2 %0, %1, %2, %0;" : "+l"(d) : "l"(a), "l"(b));
}
__device__ __forceinline__ u64 mul2(u64 a, u64 b) {
    u64 r; asm("mul.rn.f32x2 %0, %1, %2;" : "=l"(r) : "l"(a), "l"(b));
    return r;
}
__device__ __forceinline__ u64 add2(u64 a, u64 b) {
    u64 r; asm("add.rn.f32x2 %0, %1, %2;" : "=l"(r) : "l"(a), "l"(b));
    return r;
}
// negate both packed floats (sign-bit xor); x + (-y) == x - y exactly (rn)
__device__ __forceinline__ u64 neg2(u64 a) {
    return a ^ 0x8000000080000000ull;
}

// ---------------------------------------------------------------------------
// Kernel 1: fused  h1 = x_t @ W1^T + b1 ; LIF over t  -> spk1, mem1
// Grid: (BATCH/BM, NHID/BN), 256 threads, 8x8 per-thread tile.
// Dynamic SMEM (96 KB): 2 double-buffered 16x128 tiles for x and W (32 KB)
//                       + persistent membrane 128x128 (64 KB)
// Accumulation: per 16-k tile FMA chain (q; k=0 via mul2 == fma into 0),
// folded into (s, nc) with Neumaier/Kahan compensation; h = s + c.
// ---------------------------------------------------------------------------
__global__ void __launch_bounds__(256, 1) snn_l1(
    const float* __restrict__ x, const float* __restrict__ W1,
    const float* __restrict__ b1, float* __restrict__ out)
{
    extern __shared__ float sm[];
    float* msm = sm + 8192;

    const int tid  = threadIdx.x;
    const int b0   = blockIdx.x * BM;
    const int n0   = blockIdx.y * BN;
    const int row0 = (tid >> 4) * 8;
    const int col0 = (tid & 15) * 8;

    const int li0 = tid >> 2;          // rows 0..63 ; second row = li0+64
    const int lk0 = (tid & 3) * 4;     // k offset within tile (0,4,8,12)

    // bias (added AFTER the K accumulation)
    float bcol[8];
#pragma unroll
    for (int j = 0; j < 8; j++) bcol[j] = b1[n0 + col0 + j];

    // init membrane
#pragma unroll
    for (int e = 0; e < 64; e++) msm[e*256 + tid] = 0.0f;

    const float4 z4 = make_float4(0.f, 0.f, 0.f, 0.f);
    float4 xr0, xr1, wr0, wr1;

    // prefetch tile (t=0, kt=0)
    {
        const int k = lk0;
        xr0 = *(const float4*)&x[(size_t)(b0 + li0)      * NIN + k];
        xr1 = *(const float4*)&x[(size_t)(b0 + li0 + 64) * NIN + k];
        wr0 = *(const float4*)&W1[(size_t)(n0 + li0)      * NIN + k];
        wr1 = *(const float4*)&W1[(size_t)(n0 + li0 + 64) * NIN + k];
    }
    {
        float* xs = sm;        float* ws = sm + 2048;
        xs[(lk0+0)*128 + li0] = xr0.x; xs[(lk0+1)*128 + li0] = xr0.y;
        xs[(lk0+2)*128 + li0] = xr0.z; xs[(lk0+3)*128 + li0] = xr0.w;
        xs[(lk0+0)*128 + li0+64] = xr1.x; xs[(lk0+1)*128 + li0+64] = xr1.y;
        xs[(lk0+2)*128 + li0+64] = xr1.z; xs[(lk0+3)*128 + li0+64] = xr1.w;
        ws[(lk0+0)*128 + li0] = wr0.x; ws[(lk0+1)*128 + li0] = wr0.y;
        ws[(lk0+2)*128 + li0] = wr0.z; ws[(lk0+3)*128 + li0] = wr0.w;
        ws[(lk0+0)*128 + li0+64] = wr1.x; ws[(lk0+1)*128 + li0+64] = wr1.y;
        ws[(lk0+2)*128 + li0+64] = wr1.z; ws[(lk0+3)*128 + li0+64] = wr1.w;
    }
    __syncthreads();

    u64 s[8][4];    // running sum
    u64 nc[8][4];   // NEGATED compensation (c = -nc)
    int cur = 0, t = 0, kt = 0;

    for (int idx = 0; idx < NS * NKT; ++idx) {
        int nt = t, nkt = kt + 1;
        if (nkt == NKT) { nkt = 0; nt++; }
        const bool more = (idx + 1 < NS * NKT);

        // prefetch next tile into registers (latency hidden by compute)
        if (more) {
            const int k = nkt * KT + lk0;
            const float* xt = x + (size_t)nt * BATCH * NIN;
            if (k < NIN) {
                xr0 = *(const float4*)&xt[(size_t)(b0 + li0)      * NIN + k];
                xr1 = *(const float4*)&xt[(size_t)(b0 + li0 + 64) * NIN + k];
                wr0 = *(const float4*)&W1[(size_t)(n0 + li0)      * NIN + k];
                wr1 = *(const float4*)&W1[(size_t)(n0 + li0 + 64) * NIN + k];
            } else {
                xr0 = z4; xr1 = z4; wr0 = z4; wr1 = z4;
            }
        }

        if (kt == 0) {
#pragma unroll
            for (int i = 0; i < 8; i++)
#pragma unroll
                for (int jp = 0; jp < 4; jp++) { s[i][jp] = 0ull; nc[i][jp] = 0ull; }
        }

        // compute on current buffer: per-tile accumulator q
        // k==0 uses mul2 (exactly fma into zero) -> no zero-init MOVs needed
        u64 q[8][4];
        {
            const float* xs = sm + cur * 4096;
            const float* ws = xs + 2048;
#pragma unroll
            for (int k = 0; k < KT; k++) {
                const float* xk = &xs[k*128 + row0];
                u64 xb[8];
                float2 p;
                p = *(const float2*)&xk[0]; xb[0] = bcast2(p.x); xb[1] = bcast2(p.y);
                p = *(const float2*)&xk[2]; xb[2] = bcast2(p.x); xb[3] = bcast2(p.y);
                p = *(const float2*)&xk[4]; xb[4] = bcast2(p.x); xb[5] = bcast2(p.y);
                p = *(const float2*)&xk[6]; xb[6] = bcast2(p.x); xb[7] = bcast2(p.y);
                const float* wk = &ws[k*128 + col0];
                u64 wp[4];
                wp[0] = *(const u64*)&wk[0];
                wp[1] = *(const u64*)&wk[2];
                wp[2] = *(const u64*)&wk[4];
                wp[3] = *(const u64*)&wk[6];
                if (k == 0) {
#pragma unroll
                    for (int i = 0; i < 8; i++)
#pragma unroll
                        for (int jp = 0; jp < 4; jp++)
                            q[i][jp] = mul2(xb[i], wp[jp]);
                } else {
#pragma unroll
                    for (int i = 0; i < 8; i++)
#pragma unroll
                        for (int jp = 0; jp < 4; jp++)
                            fma2(q[i][jp], xb[i], wp[jp]);
                }
            }
        }
        // Kahan/Neumaier fold of tile sum q into (s, nc):
        //   y = q + nc; t = s + y; d = t - s; nc = y - d; s = t
#pragma unroll
        for (int i = 0; i < 8; i++)
#pragma unroll
            for (int jp = 0; jp < 4; jp++) {
                u64 y  = add2(q[i][jp], nc[i][jp]);
                u64 tt = add2(s[i][jp], y);
                u64 d  = add2(tt, neg2(s[i][jp]));
                nc[i][jp] = add2(y, neg2(d));
                s[i][jp] = tt;
            }

        // end of K: LIF update for timestep t, write spk1 / mem1
        if (kt == NKT - 1) {
            const size_t ob = ((size_t)t * BATCH + (b0 + row0)) * NHID + n0 + col0;
#pragma unroll
            for (int i = 0; i < 8; i++) {
                float h[8];
#pragma unroll
                for (int jp = 0; jp < 4; jp++) {
                    u64 hs = add2(s[i][jp], neg2(nc[i][jp]));   // s + c
                    upk2(hs, h[2*jp], h[2*jp+1]);
                }
                float sv[8], mv[8];
#pragma unroll
                for (int j = 0; j < 8; j++) {
                    float hb = __fadd_rn(h[j], bcol[j]);        // gemm + bias
                    float mm = msm[(i*8 + j)*256 + tid];
                    mm = __fadd_rn(__fmul_rn(0.9f, mm), hb);    // beta*m + h
                    float spk = (mm - 1.0f > 0.0f) ? 1.0f : 0.0f;
                    mm = __fadd_rn(mm, -spk);                    // soft reset
                    msm[(i*8 + j)*256 + tid] = mm;
                    sv[j] = spk; mv[j] = mm;
                }
                float* o1 = out + SPK1_OFF + ob + (size_t)i * NHID;
                *(float4*)&o1[0] = make_float4(sv[0], sv[1], sv[2], sv[3]);
                *(float4*)&o1[4] = make_float4(sv[4], sv[5], sv[6], sv[7]);
                float* o2 = out + MEM1_OFF + ob + (size_t)i * NHID;
                *(float4*)&o2[0] = make_float4(mv[0], mv[1], mv[2], mv[3]);
                *(float4*)&o2[4] = make_float4(mv[4], mv[5], mv[6], mv[7]);
            }
        }

        // stage next tile into the other buffer
        if (more) {
            float* xs = sm + (cur ^ 1) * 4096;
            float* ws = xs + 2048;
            xs[(lk0+0)*128 + li0] = xr0.x; xs[(lk0+1)*128 + li0] = xr0.y;
            xs[(lk0+2)*128 + li0] = xr0.z; xs[(lk0+3)*128 + li0] = xr0.w;
            xs[(lk0+0)*128 + li0+64] = xr1.x; xs[(lk0+1)*128 + li0+64] = xr1.y;
            xs[(lk0+2)*128 + li0+64] = xr1.z; xs[(lk0+3)*128 + li0+64] = xr1.w;
            ws[(lk0+0)*128 + li0] = wr0.x; ws[(lk0+1)*128 + li0] = wr0.y;
            ws[(lk0+2)*128 + li0] = wr0.z; ws[(lk0+3)*128 + li0] = wr0.w;
            ws[(lk0+0)*128 + li0+64] = wr1.x; ws[(lk0+1)*128 + li0+64] = wr1.y;
            ws[(lk0+2)*128 + li0+64] = wr1.z; ws[(lk0+3)*128 + li0+64] = wr1.w;
        }
        __syncthreads();
        cur ^= 1; t = nt; kt = nkt;
    }
}

// ---------------------------------------------------------------------------
// Kernel 2: fused  h2 = spk1_t @ W2^T + b2 ; LIF over t  -> spk2, mem2
// Thread per (row, output); 512 CTAs x 160 threads (16 rows x 10 outputs).
// Spike staging via cp.async, double-buffered across timesteps so the DRAM
// read of t+1 overlaps the compute of t. Per-thread chain identical to the
// round-6/7 kernel (single fp32 acc, k = 0..255 ascending) -> bit-exact.
// ---------------------------------------------------------------------------
#define L2_ROWS 16
#define L2_TPB  (L2_ROWS * NOUTN)   // 160
#define SP_STRIDE 264               // 256 + 8 pad (float4-aligned, bank-safe)
#define W2_STRIDE 260               // 256 + 4 pad

__device__ __forceinline__ void cp_async16(unsigned int smem_dst, const void* gsrc) {
    asm volatile("cp.async.cg.shared.global [%0], [%1], 16;\n"
                 :: "r"(smem_dst), "l"(gsrc));
}
__device__ __forceinline__ void cp_commit() {
    asm volatile("cp.async.commit_group;\n");
}
__device__ __forceinline__ void cp_wait0() {
    asm volatile("cp.async.wait_group 0;\n");
}

__global__ void __launch_bounds__(L2_TPB) snn_l2(
    float* __restrict__ out, const float* __restrict__ W2,
    const float* __restrict__ b2)
{
    __shared__ float w2s[NOUTN * W2_STRIDE];
    __shared__ float sps[2][L2_ROWS * SP_STRIDE];

    const int tid = threadIdx.x;
    const int r   = tid / NOUTN;          // local row 0..15
    const int o   = tid % NOUTN;          // output 0..9
    const int row = blockIdx.x * L2_ROWS + r;

    // load W2 into padded SMEM
    for (int i = tid; i < NOUTN * NHID; i += L2_TPB) {
        int oo = i / NHID, kk = i % NHID;
        w2s[oo * W2_STRIDE + kk] = W2[i];
    }
    const float bo = b2[o];

    const unsigned int sps_u32 =
        (unsigned int)__cvta_generic_to_shared(&sps[0][0]);
    const unsigned int BUFB = L2_ROWS * SP_STRIDE * 4;   // bytes per buffer

    // prefetch t=0 into buffer 0
    {
        const float4* src = (const float4*)(out + SPK1_OFF +
            ((size_t)blockIdx.x * L2_ROWS) * NHID);
        for (int i = tid; i < L2_ROWS * (NHID/4); i += L2_TPB) {
            int rr = i >> 6, kk = i & 63;
            cp_async16(sps_u32 + (unsigned int)(rr * SP_STRIDE + kk * 4) * 4,
                       src + i);
        }
        cp_commit();
    }

    float m2 = 0.0f;
    int buf = 0;

    for (int t = 0; t < NS; t++) {
        cp_wait0();
        __syncthreads();   // buffer `buf` filled; prior reads of other buf done

        // prefetch t+1 into the other buffer
        if (t + 1 < NS) {
            const float4* src = (const float4*)(out + SPK1_OFF +
                ((size_t)(t + 1) * BATCH + (size_t)blockIdx.x * L2_ROWS) * NHID);
            const unsigned int dst0 = sps_u32 + (buf ^ 1) * BUFB;
            for (int i = tid; i < L2_ROWS * (NHID/4); i += L2_TPB) {
                int rr = i >> 6, kk = i & 63;
                cp_async16(dst0 + (unsigned int)(rr * SP_STRIDE + kk * 4) * 4,
                           src + i);
            }
            cp_commit();
        }

        // serial ascending-k chain: acc = fma(s_k, w_k, acc), k = 0..255
        float acc = 0.0f;
        const float* sp = &sps[buf][r * SP_STRIDE];
        const float* wo = &w2s[o * W2_STRIDE];
#pragma unroll
        for (int kc = 0; kc < NHID / 4; kc++) {
            float4 v = *(const float4*)&sp[kc * 4];
            float4 w = *(const float4*)&wo[kc * 4];
            acc = fmaf(v.x, w.x, acc);
            acc = fmaf(v.y, w.y, acc);
            acc = fmaf(v.z, w.z, acc);
            acc = fmaf(v.w, w.w, acc);
        }

        float h = __fadd_rn(acc, bo);                 // gemm + bias
        m2 = __fadd_rn(__fmul_rn(0.9f, m2), h);       // beta*m + h
        float spk = (m2 - 1.0f > 0.0f) ? 1.0f : 0.0f;
        m2 = __fadd_rn(m2, -spk);                     // soft reset

        const size_t ob = ((size_t)t * BATCH + row) * NOUTN + o;
        out[SPK2_OFF + ob] = spk;
        out[MEM2_OFF + ob] = m2;

        __syncthreads();   // all reads of `buf` done before it's refilled
        buf ^= 1;
    }
}

// ---------------------------------------------------------------------------
extern "C" void kernel_launch(void* const* d_in, const int* in_sizes, int n_in,
                              void* d_out, int out_size)
{
    const float* x  = (const float*)d_in[0];
    const float* W1 = (const float*)d_in[1];
    const float* b1 = (const float*)d_in[2];
    const float* W2 = (const float*)d_in[3];
    const float* b2 = (const float*)d_in[4];
    float* out = (float*)d_out;

    cudaFuncSetAttribute(snn_l1, cudaFuncAttributeMaxDynamicSharedMemorySize,
                         96 * 1024);

    dim3 g1(BATCH / BM, NHID / BN);
    snn_l1<<<g1, 256, 96 * 1024>>>(x, W1, b1, out);
    snn_l2<<<BATCH / L2_ROWS, L2_TPB>>>(out, W2, b2);
}

// round 10
// speedup vs baseline: 1.1660x; 1.0192x over previous
#include <cuda_runtime.h>
#include <cstdint>

// ---------------------------------------------------------------------------
// SNN: 20 steps, batch 8192, 676 -> 256 (LIF) -> 10 (LIF)
// Outputs concatenated in tuple order: spk2, spk1, mem2, mem1 (fp32)
//
// NUMERICS (passing since round 6, rel_err ~6e-4):
//   * layer-1: ascending-k fma2 chains + Kahan-compensated folds
//     (round 10: fold every 4 tiles = 64-k chains; drift analysis says
//      our sigma stays below the reference's own rounding sigma)
//   * layer-2: serial ascending-k fp32 fmaf chain, single accumulator
//   * bias after GEMM; LIF beta*m+h as separate mul/add; sub-reset
// Round 10 scheduling: l2 triple-buffered cp.async (prefetch depth 2).
// ---------------------------------------------------------------------------

#define NS    20
#define BATCH 8192
#define NIN   676
#define NHID  256
#define NOUTN 10

#define KT  16
#define NKT 43          // ceil(676/16)
#define BM  128
#define BN  128

#define SPK2_OFF 0ull
#define SPK1_OFF (20ull*8192*10)
#define MEM2_OFF (SPK1_OFF + 20ull*8192*256)
#define MEM1_OFF (MEM2_OFF + 20ull*8192*10)

typedef unsigned long long u64;

__device__ __forceinline__ u64 bcast2(float x) {
    u64 r; asm("mov.b64 %0, {%1, %1};" : "=l"(r) : "f"(x)); return r;
}
__device__ __forceinline__ void upk2(u64 v, float& a, float& b) {
    asm("mov.b64 {%0, %1}, %2;" : "=f"(a), "=f"(b) : "l"(v));
}
__device__ __forceinline__ void fma2(u64& d, u64 a, u64 b) {
    asm("fma.rn.f32x2 %0, %1, %2, %0;" : "+l"(d) : "l"(a), "l"(b));
}
__device__ __forceinline__ u64 mul2(u64 a, u64 b) {
    u64 r; asm("mul.rn.f32x2 %0, %1, %2;" : "=l"(r) : "l"(a), "l"(b));
    return r;
}
__device__ __forceinline__ u64 add2(u64 a, u64 b) {
    u64 r; asm("add.rn.f32x2 %0, %1, %2;" : "=l"(r) : "l"(a), "l"(b));
    return r;
}
// negate both packed floats (sign-bit xor); x + (-y) == x - y exactly (rn)
__device__ __forceinline__ u64 neg2(u64 a) {
    return a ^ 0x8000000080000000ull;
}

// ---------------------------------------------------------------------------
// Kernel 1: fused  h1 = x_t @ W1^T + b1 ; LIF over t  -> spk1, mem1
// Grid: (BATCH/BM, NHID/BN), 256 threads, 8x8 per-thread tile.
// Dynamic SMEM (96 KB): 2 double-buffered 16x128 tiles for x and W (32 KB)
//                       + persistent membrane 128x128 (64 KB)
// Accumulation: ascending-k fma2 chain q spanning a GROUP of 4 tiles
// (64 k, first k via mul2 == fma into 0), folded into (s, nc) with
// Neumaier/Kahan compensation at group end; h = s + c.
// Groups: [0..3],[4..7],...,[36..39],[40..42].
// ---------------------------------------------------------------------------
__global__ void __launch_bounds__(256, 1) snn_l1(
    const float* __restrict__ x, const float* __restrict__ W1,
    const float* __restrict__ b1, float* __restrict__ out)
{
    extern __shared__ float sm[];
    float* msm = sm + 8192;

    const int tid  = threadIdx.x;
    const int b0   = blockIdx.x * BM;
    const int n0   = blockIdx.y * BN;
    const int row0 = (tid >> 4) * 8;
    const int col0 = (tid & 15) * 8;

    const int li0 = tid >> 2;          // rows 0..63 ; second row = li0+64
    const int lk0 = (tid & 3) * 4;     // k offset within tile (0,4,8,12)

    // bias (added AFTER the K accumulation)
    float bcol[8];
#pragma unroll
    for (int j = 0; j < 8; j++) bcol[j] = b1[n0 + col0 + j];

    // init membrane
#pragma unroll
    for (int e = 0; e < 64; e++) msm[e*256 + tid] = 0.0f;

    const float4 z4 = make_float4(0.f, 0.f, 0.f, 0.f);
    float4 xr0, xr1, wr0, wr1;

    // prefetch tile (t=0, kt=0)
    {
        const int k = lk0;
        xr0 = *(const float4*)&x[(size_t)(b0 + li0)      * NIN + k];
        xr1 = *(const float4*)&x[(size_t)(b0 + li0 + 64) * NIN + k];
        wr0 = *(const float4*)&W1[(size_t)(n0 + li0)      * NIN + k];
        wr1 = *(const float4*)&W1[(size_t)(n0 + li0 + 64) * NIN + k];
    }
    {
        float* xs = sm;        float* ws = sm + 2048;
        xs[(lk0+0)*128 + li0] = xr0.x; xs[(lk0+1)*128 + li0] = xr0.y;
        xs[(lk0+2)*128 + li0] = xr0.z; xs[(lk0+3)*128 + li0] = xr0.w;
        xs[(lk0+0)*128 + li0+64] = xr1.x; xs[(lk0+1)*128 + li0+64] = xr1.y;
        xs[(lk0+2)*128 + li0+64] = xr1.z; xs[(lk0+3)*128 + li0+64] = xr1.w;
        ws[(lk0+0)*128 + li0] = wr0.x; ws[(lk0+1)*128 + li0] = wr0.y;
        ws[(lk0+2)*128 + li0] = wr0.z; ws[(lk0+3)*128 + li0] = wr0.w;
        ws[(lk0+0)*128 + li0+64] = wr1.x; ws[(lk0+1)*128 + li0+64] = wr1.y;
        ws[(lk0+2)*128 + li0+64] = wr1.z; ws[(lk0+3)*128 + li0+64] = wr1.w;
    }
    __syncthreads();

    u64 s[8][4];    // running sum
    u64 nc[8][4];   // NEGATED compensation (c = -nc)
    u64 q[8][4];    // current group chain (persists across tiles in group)
    int cur = 0, t = 0, kt = 0;

    for (int idx = 0; idx < NS * NKT; ++idx) {
        int nt = t, nkt = kt + 1;
        if (nkt == NKT) { nkt = 0; nt++; }
        const bool more = (idx + 1 < NS * NKT);

        // prefetch next tile into registers (latency hidden by compute)
        if (more) {
            const int k = nkt * KT + lk0;
            const float* xt = x + (size_t)nt * BATCH * NIN;
            if (k < NIN) {
                xr0 = *(const float4*)&xt[(size_t)(b0 + li0)      * NIN + k];
                xr1 = *(const float4*)&xt[(size_t)(b0 + li0 + 64) * NIN + k];
                wr0 = *(const float4*)&W1[(size_t)(n0 + li0)      * NIN + k];
                wr1 = *(const float4*)&W1[(size_t)(n0 + li0 + 64) * NIN + k];
            } else {
                xr0 = z4; xr1 = z4; wr0 = z4; wr1 = z4;
            }
        }

        if (kt == 0) {
#pragma unroll
            for (int i = 0; i < 8; i++)
#pragma unroll
                for (int jp = 0; jp < 4; jp++) { s[i][jp] = 0ull; nc[i][jp] = 0ull; }
        }

        const bool fresh = ((kt & 3) == 0);          // first tile of group
        const bool fold  = ((kt & 3) == 3) || (kt == NKT - 1);

        // accumulate this tile into the group chain q (k ascending)
        {
            const float* xs = sm + cur * 4096;
            const float* ws = xs + 2048;
#pragma unroll
            for (int k = 0; k < KT; k++) {
                const float* xk = &xs[k*128 + row0];
                u64 xb[8];
                float2 p;
                p = *(const float2*)&xk[0]; xb[0] = bcast2(p.x); xb[1] = bcast2(p.y);
                p = *(const float2*)&xk[2]; xb[2] = bcast2(p.x); xb[3] = bcast2(p.y);
                p = *(const float2*)&xk[4]; xb[4] = bcast2(p.x); xb[5] = bcast2(p.y);
                p = *(const float2*)&xk[6]; xb[6] = bcast2(p.x); xb[7] = bcast2(p.y);
                const float* wk = &ws[k*128 + col0];
                u64 wp[4];
                wp[0] = *(const u64*)&wk[0];
                wp[1] = *(const u64*)&wk[2];
                wp[2] = *(const u64*)&wk[4];
                wp[3] = *(const u64*)&wk[6];
                if (k == 0 && fresh) {
#pragma unroll
                    for (int i = 0; i < 8; i++)
#pragma unroll
                        for (int jp = 0; jp < 4; jp++)
                            q[i][jp] = mul2(xb[i], wp[jp]);
                } else {
#pragma unroll
                    for (int i = 0; i < 8; i++)
#pragma unroll
                        for (int jp = 0; jp < 4; jp++)
                            fma2(q[i][jp], xb[i], wp[jp]);
                }
            }
        }

        // group end: Kahan/Neumaier fold of chain q into (s, nc)
        //   y = q + nc; t = s + y; d = t - s; nc = y - d; s = t
        if (fold) {
#pragma unroll
            for (int i = 0; i < 8; i++)
#pragma unroll
                for (int jp = 0; jp < 4; jp++) {
                    u64 y  = add2(q[i][jp], nc[i][jp]);
                    u64 tt = add2(s[i][jp], y);
                    u64 d  = add2(tt, neg2(s[i][jp]));
                    nc[i][jp] = add2(y, neg2(d));
                    s[i][jp] = tt;
                }
        }

        // end of K: LIF update for timestep t, write spk1 / mem1
        if (kt == NKT - 1) {
            const size_t ob = ((size_t)t * BATCH + (b0 + row0)) * NHID + n0 + col0;
#pragma unroll
            for (int i = 0; i < 8; i++) {
                float h[8];
#pragma unroll
                for (int jp = 0; jp < 4; jp++) {
                    u64 hs = add2(s[i][jp], neg2(nc[i][jp]));   // s + c
                    upk2(hs, h[2*jp], h[2*jp+1]);
                }
                float sv[8], mv[8];
#pragma unroll
                for (int j = 0; j < 8; j++) {
                    float hb = __fadd_rn(h[j], bcol[j]);        // gemm + bias
                    float mm = msm[(i*8 + j)*256 + tid];
                    mm = __fadd_rn(__fmul_rn(0.9f, mm), hb);    // beta*m + h
                    float spk = (mm - 1.0f > 0.0f) ? 1.0f : 0.0f;
                    mm = __fadd_rn(mm, -spk);                    // soft reset
                    msm[(i*8 + j)*256 + tid] = mm;
                    sv[j] = spk; mv[j] = mm;
                }
                float* o1 = out + SPK1_OFF + ob + (size_t)i * NHID;
                *(float4*)&o1[0] = make_float4(sv[0], sv[1], sv[2], sv[3]);
                *(float4*)&o1[4] = make_float4(sv[4], sv[5], sv[6], sv[7]);
                float* o2 = out + MEM1_OFF + ob + (size_t)i * NHID;
                *(float4*)&o2[0] = make_float4(mv[0], mv[1], mv[2], mv[3]);
                *(float4*)&o2[4] = make_float4(mv[4], mv[5], mv[6], mv[7]);
            }
        }

        // stage next tile into the other buffer
        if (more) {
            float* xs = sm + (cur ^ 1) * 4096;
            float* ws = xs + 2048;
            xs[(lk0+0)*128 + li0] = xr0.x; xs[(lk0+1)*128 + li0] = xr0.y;
            xs[(lk0+2)*128 + li0] = xr0.z; xs[(lk0+3)*128 + li0] = xr0.w;
            xs[(lk0+0)*128 + li0+64] = xr1.x; xs[(lk0+1)*128 + li0+64] = xr1.y;
            xs[(lk0+2)*128 + li0+64] = xr1.z; xs[(lk0+3)*128 + li0+64] = xr1.w;
            ws[(lk0+0)*128 + li0] = wr0.x; ws[(lk0+1)*128 + li0] = wr0.y;
            ws[(lk0+2)*128 + li0] = wr0.z; ws[(lk0+3)*128 + li0] = wr0.w;
            ws[(lk0+0)*128 + li0+64] = wr1.x; ws[(lk0+1)*128 + li0+64] = wr1.y;
            ws[(lk0+2)*128 + li0+64] = wr1.z; ws[(lk0+3)*128 + li0+64] = wr1.w;
        }
        __syncthreads();
        cur ^= 1; t = nt; kt = nkt;
    }
}

// ---------------------------------------------------------------------------
// Kernel 2: fused  h2 = spk1_t @ W2^T + b2 ; LIF over t  -> spk2, mem2
// Thread per (row, output); 512 CTAs x 160 threads (16 rows x 10 outputs).
// Spike staging via cp.async, TRIPLE-buffered (prefetch depth 2) so two
// timesteps of DRAM reads are in flight. Per-thread chain identical to
// round 6-9 (single fp32 acc, k = 0..255 ascending) -> bit-exact.
// ---------------------------------------------------------------------------
#define L2_ROWS 16
#define L2_TPB  (L2_ROWS * NOUTN)   // 160
#define SP_STRIDE 264               // 256 + 8 pad (float4-aligned, bank-safe)
#define W2_STRIDE 260               // 256 + 4 pad

__device__ __forceinline__ void cp_async16(unsigned int smem_dst, const void* gsrc) {
    asm volatile("cp.async.cg.shared.global [%0], [%1], 16;\n"
                 :: "r"(smem_dst), "l"(gsrc));
}
__device__ __forceinline__ void cp_commit() {
    asm volatile("cp.async.commit_group;\n");
}
__device__ __forceinline__ void cp_wait0() {
    asm volatile("cp.async.wait_group 0;\n");
}
__device__ __forceinline__ void cp_wait1() {
    asm volatile("cp.async.wait_group 1;\n");
}

__global__ void __launch_bounds__(L2_TPB) snn_l2(
    float* __restrict__ out, const float* __restrict__ W2,
    const float* __restrict__ b2)
{
    __shared__ float w2s[NOUTN * W2_STRIDE];
    __shared__ float sps[3][L2_ROWS * SP_STRIDE];

    const int tid = threadIdx.x;
    const int r   = tid / NOUTN;          // local row 0..15
    const int o   = tid % NOUTN;          // output 0..9
    const int row = blockIdx.x * L2_ROWS + r;

    // load W2 into padded SMEM
    for (int i = tid; i < NOUTN * NHID; i += L2_TPB) {
        int oo = i / NHID, kk = i % NHID;
        w2s[oo * W2_STRIDE + kk] = W2[i];
    }
    const float bo = b2[o];

    const unsigned int sps_u32 =
        (unsigned int)__cvta_generic_to_shared(&sps[0][0]);
    const unsigned int BUFB = L2_ROWS * SP_STRIDE * 4;   // bytes per buffer

    // prefetch t=0 (buf 0) and t=1 (buf 1)
#pragma unroll
    for (int pf = 0; pf < 2; pf++) {
        const float4* src = (const float4*)(out + SPK1_OFF +
            ((size_t)pf * BATCH + (size_t)blockIdx.x * L2_ROWS) * NHID);
        const unsigned int dst0 = sps_u32 + pf * BUFB;
        for (int i = tid; i < L2_ROWS * (NHID/4); i += L2_TPB) {
            int rr = i >> 6, kk = i & 63;
            cp_async16(dst0 + (unsigned int)(rr * SP_STRIDE + kk * 4) * 4,
                       src + i);
        }
        cp_commit();
    }

    float m2 = 0.0f;

    for (int t = 0; t < NS; t++) {
        if (t + 1 < NS) cp_wait1(); else cp_wait0();
        __syncthreads();   // buf t%3 filled; all reads of buf (t+2)%3 done

        // prefetch t+2 into buffer (t+2)%3 (that buffer was consumed at t-1)
        if (t + 2 < NS) {
            const float4* src = (const float4*)(out + SPK1_OFF +
                ((size_t)(t + 2) * BATCH + (size_t)blockIdx.x * L2_ROWS) * NHID);
            const unsigned int dst0 = sps_u32 + ((t + 2) % 3) * BUFB;
            for (int i = tid; i < L2_ROWS * (NHID/4); i += L2_TPB) {
                int rr = i >> 6, kk = i & 63;
                cp_async16(dst0 + (unsigned int)(rr * SP_STRIDE + kk * 4) * 4,
                           src + i);
            }
            cp_commit();
        }

        // serial ascending-k chain: acc = fma(s_k, w_k, acc), k = 0..255
        float acc = 0.0f;
        const float* sp = &sps[t % 3][r * SP_STRIDE];
        const float* wo = &w2s[o * W2_STRIDE];
#pragma unroll
        for (int kc = 0; kc < NHID / 4; kc++) {
            float4 v = *(const float4*)&sp[kc * 4];
            float4 w = *(const float4*)&wo[kc * 4];
            acc = fmaf(v.x, w.x, acc);
            acc = fmaf(v.y, w.y, acc);
            acc = fmaf(v.z, w.z, acc);
            acc = fmaf(v.w, w.w, acc);
        }

        float h = __fadd_rn(acc, bo);                 // gemm + bias
        m2 = __fadd_rn(__fmul_rn(0.9f, m2), h);       // beta*m + h
        float spk = (m2 - 1.0f > 0.0f) ? 1.0f : 0.0f;
        m2 = __fadd_rn(m2, -spk);                     // soft reset

        const size_t ob = ((size_t)t * BATCH + row) * NOUTN + o;
        out[SPK2_OFF + ob] = spk;
        out[MEM2_OFF + ob] = m2;

        __syncthreads();   // all reads of buf t%3 done before refill at t+1
    }
}

// ---------------------------------------------------------------------------
extern "C" void kernel_launch(void* const* d_in, const int* in_sizes, int n_in,
                              void* d_out, int out_size)
{
    const float* x  = (const float*)d_in[0];
    const float* W1 = (const float*)d_in[1];
    const float* b1 = (const float*)d_in[2];
    const float* W2 = (const float*)d_in[3];
    const float* b2 = (const float*)d_in[4];
    float* out = (float*)d_out;

    cudaFuncSetAttribute(snn_l1, cudaFuncAttributeMaxDynamicSharedMemorySize,
                         96 * 1024);

    dim3 g1(BATCH / BM, NHID / BN);
    snn_l1<<<g1, 256, 96 * 1024>>>(x, W1, b1, out);
    snn_l2<<<BATCH / L2_ROWS, L2_TPB>>>(out, W2, b2);
}